// round 12
// baseline (speedup 1.0000x reference)
#include <cuda_runtime.h>
#include <cuda_bf16.h>
#include <cstdint>

// ---------------- problem constants ----------------
#define C       128
#define HW      (512 * 512)
#define BATCH   4
#define TILE_PX 64
#define TILES_PER_B (HW / TILE_PX)      // 4096
#define NT      (BATCH * TILES_PER_B)   // 16384
#define THREADS 256
#define GRID    148

// ---------------- smem layout ----------------
#define W_PITCH_B  272                  // 17*16: ldsm-legal, conflict-free
#define W_PLANE_B  (C * W_PITCH_B)      // 34816
#define S_W        0                    // hi plane; lo at +W_PLANE_B
// X: 2 stages x (hi plane + lo plane); [k][px] bf16 rows, pitch 144B (9*16)
#define X_PITCH_B  144
#define X_PLANE_B  (C * X_PITCH_B)      // 18432
#define X_STAGE_B  (2 * X_PLANE_B)      // 36864
#define S_X        (2 * W_PLANE_B)      // 69632
// epilogue scratch: 2 stages x 128 rows x 76 words (304B = 19*16)
#define SCRATCH_PITCH_W 76
#define SCR_B      (C * SCRATCH_PITCH_W * 4)   // 38912
#define S_SCR      (S_X + 2 * X_STAGE_B)       // 143360
#define SMEM_TOTAL (S_SCR + 2 * SCR_B)         // 221184

typedef unsigned long long u64;

// Masked bf16 hi/lo split of W, row-major [co][k]
__device__ __nv_bfloat16 g_Whi[C * C];
__device__ __nv_bfloat16 g_Wlo[C * C];

__global__ void build_w_kernel(const float* __restrict__ w) {
    int co = blockIdx.x;
    int k  = threadIdx.x;
    float v = ((k >> 3) <= (co >> 3)) ? w[co * C + k] : 0.0f;  // HIDDEN mask
    __nv_bfloat16 h = __float2bfloat16(v);
    float r = v - __bfloat162float(h);
    g_Whi[co * C + k] = h;
    g_Wlo[co * C + k] = __float2bfloat16(r);
}

// ---------------- helpers ----------------
__device__ __forceinline__ uint32_t smem_u32(const void* p) {
    uint32_t a;
    asm("{ .reg .u64 t; cvta.to.shared.u64 t, %1; cvt.u32.u64 %0, t; }" : "=r"(a) : "l"(p));
    return a;
}
__device__ __forceinline__ uint32_t packbf2(float a, float b) {
    uint32_t r;
    asm("cvt.rn.bf16x2.f32 %0, %1, %2;" : "=r"(r) : "f"(b), "f"(a));
    return r;
}
__device__ __forceinline__ void ldsm_x4(uint32_t* r, uint32_t a) {
    asm volatile("ldmatrix.sync.aligned.m8n8.x4.shared.b16 {%0,%1,%2,%3}, [%4];"
        : "=r"(r[0]), "=r"(r[1]), "=r"(r[2]), "=r"(r[3]) : "r"(a));
}
__device__ __forceinline__ void ldsm_x4_t(uint32_t* r, uint32_t a) {
    asm volatile("ldmatrix.sync.aligned.m8n8.x4.trans.shared.b16 {%0,%1,%2,%3}, [%4];"
        : "=r"(r[0]), "=r"(r[1]), "=r"(r[2]), "=r"(r[3]) : "r"(a));
}
__device__ __forceinline__ void mma_bf16(float* d, const uint32_t* a,
                                         uint32_t b0, uint32_t b1) {
    asm volatile("mma.sync.aligned.m16n8k16.row.col.f32.bf16.bf16.f32 "
        "{%0,%1,%2,%3}, {%4,%5,%6,%7}, {%8,%9}, {%0,%1,%2,%3};"
        : "+f"(d[0]), "+f"(d[1]), "+f"(d[2]), "+f"(d[3])
        : "r"(a[0]), "r"(a[1]), "r"(a[2]), "r"(a[3]), "r"(b0), "r"(b1));
}
__device__ __forceinline__ void mma3(float* a0, float* a1,
                                     const uint32_t* Ah, const uint32_t* Al,
                                     const uint32_t* Bh, const uint32_t* Bl) {
    mma_bf16(a0, Ah, Bh[0], Bh[1]);
    mma_bf16(a0, Ah, Bl[0], Bl[1]);
    mma_bf16(a0, Al, Bh[0], Bh[1]);
    mma_bf16(a1, Ah, Bh[2], Bh[3]);
    mma_bf16(a1, Ah, Bl[2], Bl[3]);
    mma_bf16(a1, Al, Bh[2], Bh[3]);
}

// ---------------- main persistent kernel ----------------
__global__ void __launch_bounds__(THREADS, 1)
cgconv_mma_kernel(const float* __restrict__ x,
                  const float* __restrict__ bias,
                  float* __restrict__ out)
{
    extern __shared__ char smem[];
    const uint32_t sb = smem_u32(smem);
    const int tid  = threadIdx.x;
    const int wid  = tid >> 5;      // 0..7
    const int lane = tid & 31;

    const int p  = wid & 3;         // pair id
    const int h  = wid >> 2;        // px half (32 px)
    const int m1 = p;               // small m-block
    const int m2 = 7 - p;           // large m-block (uniform 9 kb-blocks/warp)

    // ---- stage W hi/lo into smem (A-frag build only) ----
    {
        const uint4* whi = reinterpret_cast<const uint4*>(g_Whi);
        const uint4* wlo = reinterpret_cast<const uint4*>(g_Wlo);
        for (int i = tid; i < C * C / 8; i += THREADS) {
            int row = i >> 4, c = i & 15;
            *reinterpret_cast<uint4*>(smem + S_W + row * W_PITCH_B + c * 16) = whi[i];
            *reinterpret_cast<uint4*>(smem + S_W + W_PLANE_B + row * W_PITCH_B + c * 16) = wlo[i];
        }
    }
    __syncthreads();

    // ---- register-resident A fragments (built once) ----
    uint32_t A1h[4][4], A1l[4][4], A2h[8][4], A2l[8][4];
    {
        const uint32_t arow    = (uint32_t)(lane & 15) * W_PITCH_B;
        const uint32_t acolsel = (uint32_t)(lane >> 4) * 16;
        const uint32_t whi_u = sb + S_W + arow + acolsel;
        const uint32_t wlo_u = sb + S_W + W_PLANE_B + arow + acolsel;
#pragma unroll
        for (int kb = 0; kb < 4; ++kb) {
            if (kb <= m1) {
                uint32_t off = (uint32_t)m1 * 16 * W_PITCH_B + (uint32_t)kb * 32;
                ldsm_x4(A1h[kb], whi_u + off);
                ldsm_x4(A1l[kb], wlo_u + off);
            }
        }
#pragma unroll
        for (int kb = 0; kb < 8; ++kb) {
            if (kb <= m2) {
                uint32_t off = (uint32_t)m2 * 16 * W_PITCH_B + (uint32_t)kb * 32;
                ldsm_x4(A2h[kb], whi_u + off);
                ldsm_x4(A2l[kb], wlo_u + off);
            }
        }
    }

    // ---- bias ----
    const int qr = lane >> 2;
    const int qj = lane & 3;
    const float b1lo = __ldg(bias + m1 * 16 + qr);
    const float b1hi = __ldg(bias + m1 * 16 + 8 + qr);
    const float b2lo = __ldg(bias + m2 * 16 + qr);
    const float b2hi = __ldg(bias + m2 * 16 + 8 + qr);

    // ---- B ldmatrix base (stage 0; stage offset added in loop) ----
    const uint32_t brow = (uint32_t)(lane & 15) * X_PITCH_B + (uint32_t)(lane >> 4) * 16;
    const uint32_t xbase_u = sb + S_X + brow + (uint32_t)h * 64;

    // ---- producer / epilogue-reader addressing ----
    const int pk_base = 16 * wid + (lane >> 4);   // k row / ch row base
    const int pk_px   = (lane & 15) * 4;          // px offset

    // ---- prologue: load t0, convert into stage 0, load t1 ----
    uint4 pf[8];
    {
        int t0 = blockIdx.x;
        int b = t0 / TILES_PER_B;
        size_t xb = (size_t)b * C * HW + (size_t)(t0 - b * TILES_PER_B) * TILE_PX;
#pragma unroll
        for (int i = 0; i < 8; ++i)
            pf[i] = *reinterpret_cast<const uint4*>(x + xb + (size_t)(pk_base + 2 * i) * HW + pk_px);
    }
    // convert t0 -> stage 0 (visible to all at first loop sync)
#pragma unroll
    for (int i = 0; i < 8; ++i) {
        const int k = pk_base + 2 * i;
        float fx = __uint_as_float(pf[i].x);
        float fy = __uint_as_float(pf[i].y);
        float fz = __uint_as_float(pf[i].z);
        float fw = __uint_as_float(pf[i].w);
        uint32_t h0 = packbf2(fx, fy);
        uint32_t h1 = packbf2(fz, fw);
        uint32_t l0 = packbf2(fx - __uint_as_float(h0 << 16),
                              fy - __uint_as_float(h0 & 0xFFFF0000u));
        uint32_t l1 = packbf2(fz - __uint_as_float(h1 << 16),
                              fw - __uint_as_float(h1 & 0xFFFF0000u));
        uint32_t off = (uint32_t)k * X_PITCH_B + (uint32_t)(lane & 15) * 8;
        *reinterpret_cast<uint2*>(smem + S_X + off)             = make_uint2(h0, h1);
        *reinterpret_cast<uint2*>(smem + S_X + X_PLANE_B + off) = make_uint2(l0, l1);
    }
    {   // load t1 into pf
        int t1 = blockIdx.x + GRID;
        if (t1 >= NT) t1 = blockIdx.x;
        int b = t1 / TILES_PER_B;
        size_t xb = (size_t)b * C * HW + (size_t)(t1 - b * TILES_PER_B) * TILE_PX;
#pragma unroll
        for (int i = 0; i < 8; ++i)
            pf[i] = *reinterpret_cast<const uint4*>(x + xb + (size_t)(pk_base + 2 * i) * HW + pk_px);
    }

    size_t prev_obase = 0;
    int n = 0;

    for (int t = blockIdx.x; t < NT; t += GRID, ++n) {
        const int s   = n & 1;
        const int b   = t / TILES_PER_B;
        const int px0 = (t - b * TILES_PER_B) * TILE_PX;
        const size_t obase = (size_t)b * C * HW + px0;

        __syncthreads();
        // Post-sync guarantees: X(s) holds tile t; scratch(s^1) holds tile t-1;
        // all reads of X(s^1) [mma t-1] and scratch(s) [STG t-2] are complete.

        // ---- 1) STG: flush tile t-1 from scratch(s^1) ----
        if (n > 0) {
            const float* srow = reinterpret_cast<const float*>(smem + S_SCR + (1 - s) * SCR_B);
#pragma unroll
            for (int i = 0; i < 8; ++i) {
                const int ch = pk_base + 2 * i;
                float4 v = *reinterpret_cast<const float4*>(
                    srow + ch * SCRATCH_PITCH_W + pk_px);
                *reinterpret_cast<float4*>(out + prev_obase + (size_t)ch * HW + pk_px) = v;
            }
        }

        // ---- 2) convert pf (tile t+1) -> X(s^1) ----
        {
            char* xs = smem + S_X + (1 - s) * X_STAGE_B;
#pragma unroll
            for (int i = 0; i < 8; ++i) {
                const int k = pk_base + 2 * i;
                float fx = __uint_as_float(pf[i].x);
                float fy = __uint_as_float(pf[i].y);
                float fz = __uint_as_float(pf[i].z);
                float fw = __uint_as_float(pf[i].w);
                uint32_t h0 = packbf2(fx, fy);
                uint32_t h1 = packbf2(fz, fw);
                uint32_t l0 = packbf2(fx - __uint_as_float(h0 << 16),
                                      fy - __uint_as_float(h0 & 0xFFFF0000u));
                uint32_t l1 = packbf2(fz - __uint_as_float(h1 << 16),
                                      fw - __uint_as_float(h1 & 0xFFFF0000u));
                uint32_t off = (uint32_t)k * X_PITCH_B + (uint32_t)(lane & 15) * 8;
                *reinterpret_cast<uint2*>(xs + off)             = make_uint2(h0, h1);
                *reinterpret_cast<uint2*>(xs + X_PLANE_B + off) = make_uint2(l0, l1);
            }
        }

        // ---- 3) LDG: prefetch tile t+2 ----
        {
            int tn = t + 2 * GRID;
            if (tn >= NT) tn = t;
            int bn = tn / TILES_PER_B;
            size_t xb = (size_t)bn * C * HW + (size_t)(tn - bn * TILES_PER_B) * TILE_PX;
#pragma unroll
            for (int i = 0; i < 8; ++i)
                pf[i] = *reinterpret_cast<const uint4*>(x + xb + (size_t)(pk_base + 2 * i) * HW + pk_px);
        }

        // ---- 4) mma on X(s) (independent of 1-3: overlaps in issue) ----
        float acc[2][4][4];
#pragma unroll
        for (int mi = 0; mi < 2; ++mi)
#pragma unroll
            for (int j = 0; j < 4; ++j)
#pragma unroll
                for (int q = 0; q < 4; ++q) acc[mi][j][q] = 0.0f;

        const uint32_t xhi_u = xbase_u + (uint32_t)s * X_STAGE_B;
        const uint32_t xlo_u = xhi_u + X_PLANE_B;
#pragma unroll
        for (int kb = 0; kb < 8; ++kb) {
            if (kb <= m2) {
#pragma unroll
                for (int nt = 0; nt < 2; ++nt) {
                    uint32_t Bh[4], Bl[4];
                    uint32_t boff = (uint32_t)kb * 16 * X_PITCH_B + (uint32_t)nt * 32;
                    ldsm_x4_t(Bh, xhi_u + boff);
                    ldsm_x4_t(Bl, xlo_u + boff);
                    mma3(acc[1][2 * nt], acc[1][2 * nt + 1], A2h[kb], A2l[kb], Bh, Bl);
                    if (kb < 4 && kb <= m1)
                        mma3(acc[0][2 * nt], acc[0][2 * nt + 1], A1h[kb], A1l[kb], Bh, Bl);
                }
            }
        }

        // ---- 5) epilogue STS: bias + transpose into scratch(s) ----
        {
            float* scr = reinterpret_cast<float*>(smem + S_SCR + s * SCR_B);
#pragma unroll
            for (int j = 0; j < 4; ++j) {
                acc[0][j][0] += b1lo; acc[0][j][1] += b1lo;
                acc[0][j][2] += b1hi; acc[0][j][3] += b1hi;
                acc[1][j][0] += b2lo; acc[1][j][1] += b2lo;
                acc[1][j][2] += b2hi; acc[1][j][3] += b2hi;
            }
#pragma unroll
            for (int mi = 0; mi < 2; ++mi) {
                const int m = mi ? m2 : m1;
                const int ch_lo = m * 16 + qr;
#pragma unroll
                for (int j = 0; j < 4; ++j) {
                    const int px = h * 32 + 8 * j + 2 * qj;
                    *reinterpret_cast<float2*>(scr + ch_lo * SCRATCH_PITCH_W + px) =
                        make_float2(acc[mi][j][0], acc[mi][j][1]);
                    *reinterpret_cast<float2*>(scr + (ch_lo + 8) * SCRATCH_PITCH_W + px) =
                        make_float2(acc[mi][j][2], acc[mi][j][3]);
                }
            }
        }

        prev_obase = obase;
    }

    // ---- flush final tile ----
    __syncthreads();
    if (n > 0) {
        const int s_last = (n - 1) & 1;
        const float* srow = reinterpret_cast<const float*>(smem + S_SCR + s_last * SCR_B);
#pragma unroll
        for (int i = 0; i < 8; ++i) {
            const int ch = pk_base + 2 * i;
            float4 v = *reinterpret_cast<const float4*>(srow + ch * SCRATCH_PITCH_W + pk_px);
            *reinterpret_cast<float4*>(out + prev_obase + (size_t)ch * HW + pk_px) = v;
        }
    }
}

extern "C" void kernel_launch(void* const* d_in, const int* in_sizes, int n_in,
                              void* d_out, int out_size)
{
    const float* x    = (const float*)d_in[0];
    const float* w    = (const float*)d_in[1];
    const float* bias = (const float*)d_in[2];
    float* out        = (float*)d_out;

    cudaFuncSetAttribute(cgconv_mma_kernel,
                         cudaFuncAttributeMaxDynamicSharedMemorySize, SMEM_TOTAL);

    build_w_kernel<<<C, C>>>(w);
    cgconv_mma_kernel<<<GRID, THREADS, SMEM_TOTAL>>>(x, bias, out);
}

// round 13
// speedup vs baseline: 1.0089x; 1.0089x over previous
#include <cuda_runtime.h>
#include <cuda_bf16.h>
#include <cstdint>

// ---------------- problem constants ----------------
#define C       128
#define HW      (512 * 512)
#define BATCH   4
#define TILE_PX 64
#define TILES_PER_B (HW / TILE_PX)      // 4096
#define NT      (BATCH * TILES_PER_B)   // 16384
#define THREADS 512
#define GRID    148

// ---------------- smem layout ----------------
// W planes: PERMANENT (A fragments ldsm'd from here each tile for kb>=3)
#define W_PITCH_B  272                  // 17*16: ldsm-legal, conflict-free
#define W_PLANE_B  (C * W_PITCH_B)      // 34816
#define S_W        0                    // hi; lo at +W_PLANE_B
// X planes: single stage, [k][px] bf16 rows, pitch 144B (9*16)
#define X_PITCH_B  144
#define X_PLANE_B  (C * X_PITCH_B)      // 18432
#define S_X        (2 * W_PLANE_B)      // 69632 ; hi, lo at +X_PLANE_B
// epilogue scratch: 128 rows x 76 words (304B = 19*16)
#define SCRATCH_PITCH_W 76
#define SCR_B      (C * SCRATCH_PITCH_W * 4)   // 38912
#define S_SCR      (S_X + 2 * X_PLANE_B)       // 106496
#define SMEM_TOTAL (S_SCR + SCR_B)             // 145408

typedef unsigned long long u64;

// Masked bf16 hi/lo split of W, row-major [co][k]
__device__ __nv_bfloat16 g_Whi[C * C];
__device__ __nv_bfloat16 g_Wlo[C * C];

__global__ void build_w_kernel(const float* __restrict__ w) {
    int co = blockIdx.x;
    int k  = threadIdx.x;
    float v = ((k >> 3) <= (co >> 3)) ? w[co * C + k] : 0.0f;  // HIDDEN mask
    __nv_bfloat16 h = __float2bfloat16(v);
    float r = v - __bfloat162float(h);
    g_Whi[co * C + k] = h;
    g_Wlo[co * C + k] = __float2bfloat16(r);
}

// ---------------- helpers ----------------
__device__ __forceinline__ uint32_t smem_u32(const void* p) {
    uint32_t a;
    asm("{ .reg .u64 t; cvta.to.shared.u64 t, %1; cvt.u32.u64 %0, t; }" : "=r"(a) : "l"(p));
    return a;
}
__device__ __forceinline__ uint32_t packbf2(float a, float b) {
    uint32_t r;
    asm("cvt.rn.bf16x2.f32 %0, %1, %2;" : "=r"(r) : "f"(b), "f"(a));
    return r;
}
__device__ __forceinline__ void ldsm_x4(uint32_t* r, uint32_t a) {
    asm volatile("ldmatrix.sync.aligned.m8n8.x4.shared.b16 {%0,%1,%2,%3}, [%4];"
        : "=r"(r[0]), "=r"(r[1]), "=r"(r[2]), "=r"(r[3]) : "r"(a));
}
__device__ __forceinline__ void ldsm_x4_t(uint32_t* r, uint32_t a) {
    asm volatile("ldmatrix.sync.aligned.m8n8.x4.trans.shared.b16 {%0,%1,%2,%3}, [%4];"
        : "=r"(r[0]), "=r"(r[1]), "=r"(r[2]), "=r"(r[3]) : "r"(a));
}
__device__ __forceinline__ void mma_bf16(float* d, const uint32_t* a,
                                         uint32_t b0, uint32_t b1) {
    asm volatile("mma.sync.aligned.m16n8k16.row.col.f32.bf16.bf16.f32 "
        "{%0,%1,%2,%3}, {%4,%5,%6,%7}, {%8,%9}, {%0,%1,%2,%3};"
        : "+f"(d[0]), "+f"(d[1]), "+f"(d[2]), "+f"(d[3])
        : "r"(a[0]), "r"(a[1]), "r"(a[2]), "r"(a[3]), "r"(b0), "r"(b1));
}
__device__ __forceinline__ void mma3(float* a0, float* a1,
                                     const uint32_t* Ah, const uint32_t* Al,
                                     const uint32_t* Bh, const uint32_t* Bl) {
    mma_bf16(a0, Ah, Bh[0], Bh[1]);
    mma_bf16(a0, Ah, Bl[0], Bl[1]);
    mma_bf16(a0, Al, Bh[0], Bh[1]);
    mma_bf16(a1, Ah, Bh[2], Bh[3]);
    mma_bf16(a1, Ah, Bl[2], Bl[3]);
    mma_bf16(a1, Al, Bh[2], Bh[3]);
}

// SMSP-balanced m assignment: SMSP {0,1} -> m in {0,3,4,7},
// SMSP {2,3} -> m in {1,2,5,6}; per-SMSP kb work = 18 blocks.
__constant__ int c_mA[4] = {0, 3, 4, 7};
__constant__ int c_mB[4] = {1, 2, 5, 6};

// ---------------- main persistent kernel ----------------
__global__ void __launch_bounds__(THREADS, 1)
cgconv_mma_kernel(const float* __restrict__ x,
                  const float* __restrict__ bias,
                  float* __restrict__ out)
{
    extern __shared__ char smem[];
    const uint32_t sb = smem_u32(smem);
    const int tid  = threadIdx.x;
    const int wid  = tid >> 5;      // 0..15
    const int lane = tid & 31;

    const int s  = wid & 3;         // SMSP id
    const int iw = wid >> 2;        // 0..3
    const int m  = (s < 2) ? c_mA[iw] : c_mB[iw];   // m-block (16 output ch)
    const int h  = s & 1;                           // px half (32 px)

    // ---- stage W hi/lo into smem (PERMANENT) ----
    {
        const uint4* whi = reinterpret_cast<const uint4*>(g_Whi);
        const uint4* wlo = reinterpret_cast<const uint4*>(g_Wlo);
        for (int i = tid; i < C * C / 8; i += THREADS) {
            int row = i >> 4, c = i & 15;
            *reinterpret_cast<uint4*>(smem + S_W + row * W_PITCH_B + c * 16) = whi[i];
            *reinterpret_cast<uint4*>(smem + S_W + W_PLANE_B + row * W_PITCH_B + c * 16) = wlo[i];
        }
    }
    __syncthreads();

    // ---- A-frag smem addresses + small register cache (kb < 3) ----
    const uint32_t arow    = (uint32_t)(lane & 15) * W_PITCH_B;
    const uint32_t acolsel = (uint32_t)(lane >> 4) * 16;
    const uint32_t whi_u = sb + S_W + arow + acolsel;
    const uint32_t wlo_u = sb + S_W + W_PLANE_B + arow + acolsel;

    uint32_t A3h[3][4], A3l[3][4];
#pragma unroll
    for (int kb = 0; kb < 3; ++kb) {
        if (kb <= m) {
            uint32_t off = (uint32_t)m * 16 * W_PITCH_B + (uint32_t)kb * 32;
            ldsm_x4(A3h[kb], whi_u + off);
            ldsm_x4(A3l[kb], wlo_u + off);
        }
    }

    // ---- bias ----
    const int qr = lane >> 2;
    const int qj = lane & 3;
    const float b_lo = __ldg(bias + m * 16 + qr);
    const float b_hi = __ldg(bias + m * 16 + 8 + qr);

    // ---- B ldmatrix bases ----
    const uint32_t brow = (uint32_t)(lane & 15) * X_PITCH_B + (uint32_t)(lane >> 4) * 16;
    const uint32_t xhi_u = sb + S_X + brow + (uint32_t)h * 64;
    const uint32_t xlo_u = xhi_u + X_PLANE_B;

    // ---- producer / epilogue-reader addressing ----
    const int pk = tid >> 2;       // k row (producer) / ch row (reader): 0..127
    const int pq = tid & 3;        // 16-px quarter

    float* scratch = reinterpret_cast<float*>(smem + S_SCR);

    // ---- prefetch first tile: 4 uint4 = px [16*pq, +16) of row pk ----
    uint4 pf[4];
    {
        int t0 = blockIdx.x;
        int b = t0 / TILES_PER_B;
        size_t xb = (size_t)b * C * HW + (size_t)(t0 - b * TILES_PER_B) * TILE_PX
                  + (size_t)pk * HW + pq * 16;
#pragma unroll
        for (int i = 0; i < 4; ++i)
            pf[i] = *reinterpret_cast<const uint4*>(x + xb + i * 4);
    }

    size_t prev_obase = 0;
    int have_prev = 0;

    for (int t = blockIdx.x; t < NT; t += GRID) {
        const int b   = t / TILES_PER_B;
        const int px0 = (t - b * TILES_PER_B) * TILE_PX;
        const size_t obase = (size_t)b * C * HW + px0;

        __syncthreads();   // mma(t-1) X reads done; epi-STS(t-1) visible in scratch

        // ---- deferred flush: write tile t-1 results from scratch to gmem ----
        if (have_prev) {
            float* srow = scratch + pk * SCRATCH_PITCH_W + pq * 16;
            float* orow = out + prev_obase + (size_t)pk * HW + pq * 16;
#pragma unroll
            for (int i = 0; i < 4; ++i)
                *reinterpret_cast<float4*>(orow + i * 4) =
                    *reinterpret_cast<const float4*>(srow + i * 4);
        }

        // ---- convert prefetched regs (tile t) -> bf16 hi/lo X planes ----
        {
            uint32_t hi[8], lo[8];
#pragma unroll
            for (int i = 0; i < 4; ++i) {
                float fx = __uint_as_float(pf[i].x);
                float fy = __uint_as_float(pf[i].y);
                float fz = __uint_as_float(pf[i].z);
                float fw = __uint_as_float(pf[i].w);
                uint32_t h0 = packbf2(fx, fy);
                uint32_t h1 = packbf2(fz, fw);
                hi[2 * i]     = h0;
                hi[2 * i + 1] = h1;
                lo[2 * i]     = packbf2(fx - __uint_as_float(h0 << 16),
                                        fy - __uint_as_float(h0 & 0xFFFF0000u));
                lo[2 * i + 1] = packbf2(fz - __uint_as_float(h1 << 16),
                                        fw - __uint_as_float(h1 & 0xFFFF0000u));
            }
            uint32_t off = (uint32_t)pk * X_PITCH_B + (uint32_t)pq * 32;
            *reinterpret_cast<uint4*>(smem + S_X + off) =
                make_uint4(hi[0], hi[1], hi[2], hi[3]);
            *reinterpret_cast<uint4*>(smem + S_X + off + 16) =
                make_uint4(hi[4], hi[5], hi[6], hi[7]);
            *reinterpret_cast<uint4*>(smem + S_X + X_PLANE_B + off) =
                make_uint4(lo[0], lo[1], lo[2], lo[3]);
            *reinterpret_cast<uint4*>(smem + S_X + X_PLANE_B + off + 16) =
                make_uint4(lo[4], lo[5], lo[6], lo[7]);
        }
        __syncthreads();   // X(t) ready; scratch(t-1) fully flushed

        // ---- prefetch tile t+GRID (latency hidden behind mma) ----
        {
            int tn = t + GRID;
            if (tn >= NT) tn = t;
            int bn = tn / TILES_PER_B;
            size_t xb = (size_t)bn * C * HW + (size_t)(tn - bn * TILES_PER_B) * TILE_PX
                      + (size_t)pk * HW + pq * 16;
#pragma unroll
            for (int i = 0; i < 4; ++i)
                pf[i] = *reinterpret_cast<const uint4*>(x + xb + i * 4);
        }

        // ---- triangular GEMM ----
        float acc[4][4];
#pragma unroll
        for (int j = 0; j < 4; ++j)
#pragma unroll
            for (int q = 0; q < 4; ++q) acc[j][q] = 0.0f;

#pragma unroll
        for (int kb = 0; kb < 8; ++kb) {
            if (kb <= m) {
                uint32_t Ah_[4], Al_[4];
                const uint32_t* pAh;
                const uint32_t* pAl;
                if (kb < 3) {
                    pAh = A3h[kb];
                    pAl = A3l[kb];
                } else {
                    uint32_t off = (uint32_t)m * 16 * W_PITCH_B + (uint32_t)kb * 32;
                    ldsm_x4(Ah_, whi_u + off);
                    ldsm_x4(Al_, wlo_u + off);
                    pAh = Ah_;
                    pAl = Al_;
                }
#pragma unroll
                for (int nt = 0; nt < 2; ++nt) {
                    uint32_t Bh[4], Bl[4];
                    uint32_t boff = (uint32_t)kb * 16 * X_PITCH_B + (uint32_t)nt * 32;
                    ldsm_x4_t(Bh, xhi_u + boff);
                    ldsm_x4_t(Bl, xlo_u + boff);
                    mma3(acc[2 * nt], acc[2 * nt + 1], pAh, pAl, Bh, Bl);
                }
            }
        }

        // ---- epilogue: bias + transpose into scratch ----
        {
            const int ch_lo = m * 16 + qr;
#pragma unroll
            for (int j = 0; j < 4; ++j) {
                const int px = h * 32 + (j >> 1) * 16 + (j & 1) * 8 + 2 * qj;
                *reinterpret_cast<float2*>(scratch + ch_lo * SCRATCH_PITCH_W + px) =
                    make_float2(acc[j][0] + b_lo, acc[j][1] + b_lo);
                *reinterpret_cast<float2*>(scratch + (ch_lo + 8) * SCRATCH_PITCH_W + px) =
                    make_float2(acc[j][2] + b_hi, acc[j][3] + b_hi);
            }
        }

        prev_obase = obase;
        have_prev = 1;
    }

    // ---- flush final tile ----
    __syncthreads();
    if (have_prev) {
        float* srow = scratch + pk * SCRATCH_PITCH_W + pq * 16;
        float* orow = out + prev_obase + (size_t)pk * HW + pq * 16;
#pragma unroll
        for (int i = 0; i < 4; ++i)
            *reinterpret_cast<float4*>(orow + i * 4) =
                *reinterpret_cast<const float4*>(srow + i * 4);
    }
}

extern "C" void kernel_launch(void* const* d_in, const int* in_sizes, int n_in,
                              void* d_out, int out_size)
{
    const float* x    = (const float*)d_in[0];
    const float* w    = (const float*)d_in[1];
    const float* bias = (const float*)d_in[2];
    float* out        = (float*)d_out;

    cudaFuncSetAttribute(cgconv_mma_kernel,
                         cudaFuncAttributeMaxDynamicSharedMemorySize, SMEM_TOTAL);

    build_w_kernel<<<C, C>>>(w);
    cgconv_mma_kernel<<<GRID, THREADS, SMEM_TOTAL>>>(x, bias, out);
}

// round 17
// speedup vs baseline: 1.1821x; 1.1717x over previous
#include <cuda_runtime.h>
#include <cuda_bf16.h>
#include <cstdint>

// ---------------- problem constants ----------------
#define C       128
#define HW      (512 * 512)
#define BATCH   4
#define TILE_PX 64
#define TILES_PER_B (HW / TILE_PX)      // 4096
#define NT      (BATCH * TILES_PER_B)   // 16384
#define THREADS 256
#define GRID    148

// ---------------- smem layout ----------------
#define W_PITCH_B  272                  // 17*16: ldsm-legal, conflict-free
#define W_PLANE_B  (C * W_PITCH_B)      // 34816
#define S_W        0                    // hi; lo at +W_PLANE_B (A-frag build only)
#define SCRATCH_PITCH_W 76              // 304B = 19*16 (aligned, conflict-free)
#define X_PITCH_B  144                  // 9*16: ldsm-legal, conflict-free
#define X_PLANE_B  (C * X_PITCH_B)      // 18432
#define S_X        (2 * W_PLANE_B)      // 69632 ; hi, lo at +X_PLANE_B
#define SCR_B      (C * SCRATCH_PITCH_W * 4)   // 38912
#define S_SCR      (S_X + 2 * X_PLANE_B)       // 106496  (own region, W kept intact)
#define SMEM_TOTAL (S_SCR + SCR_B)             // 145408

typedef unsigned long long u64;

// Masked bf16 hi/lo split of W, row-major [co][k]
__device__ __nv_bfloat16 g_Whi[C * C];
__device__ __nv_bfloat16 g_Wlo[C * C];

__global__ void build_w_kernel(const float* __restrict__ w) {
    int co = blockIdx.x;
    int k  = threadIdx.x;
    float v = ((k >> 3) <= (co >> 3)) ? w[co * C + k] : 0.0f;  // HIDDEN mask
    __nv_bfloat16 h = __float2bfloat16(v);
    float r = v - __bfloat162float(h);
    g_Whi[co * C + k] = h;
    g_Wlo[co * C + k] = __float2bfloat16(r);
}

// ---------------- helpers ----------------
__device__ __forceinline__ uint32_t smem_u32(const void* p) {
    uint32_t a;
    asm("{ .reg .u64 t; cvta.to.shared.u64 t, %1; cvt.u32.u64 %0, t; }" : "=r"(a) : "l"(p));
    return a;
}
__device__ __forceinline__ uint32_t packbf2(float a, float b) {
    uint32_t r;
    asm("cvt.rn.bf16x2.f32 %0, %1, %2;" : "=r"(r) : "f"(b), "f"(a));
    return r;
}
__device__ __forceinline__ void ldsm_x4(uint32_t* r, uint32_t a) {
    asm volatile("ldmatrix.sync.aligned.m8n8.x4.shared.b16 {%0,%1,%2,%3}, [%4];"
        : "=r"(r[0]), "=r"(r[1]), "=r"(r[2]), "=r"(r[3]) : "r"(a));
}
__device__ __forceinline__ void ldsm_x4_t(uint32_t* r, uint32_t a) {
    asm volatile("ldmatrix.sync.aligned.m8n8.x4.trans.shared.b16 {%0,%1,%2,%3}, [%4];"
        : "=r"(r[0]), "=r"(r[1]), "=r"(r[2]), "=r"(r[3]) : "r"(a));
}
__device__ __forceinline__ void mma_bf16(float* d, const uint32_t* a,
                                         uint32_t b0, uint32_t b1) {
    asm volatile("mma.sync.aligned.m16n8k16.row.col.f32.bf16.bf16.f32 "
        "{%0,%1,%2,%3}, {%4,%5,%6,%7}, {%8,%9}, {%0,%1,%2,%3};"
        : "+f"(d[0]), "+f"(d[1]), "+f"(d[2]), "+f"(d[3])
        : "r"(a[0]), "r"(a[1]), "r"(a[2]), "r"(a[3]), "r"(b0), "r"(b1));
}
__device__ __forceinline__ void mma3(float* a0, float* a1,
                                     const uint32_t* Ah, const uint32_t* Al,
                                     const uint32_t* Bh, const uint32_t* Bl) {
    mma_bf16(a0, Ah, Bh[0], Bh[1]);
    mma_bf16(a0, Ah, Bl[0], Bl[1]);
    mma_bf16(a0, Al, Bh[0], Bh[1]);
    mma_bf16(a1, Ah, Bh[2], Bh[3]);
    mma_bf16(a1, Ah, Bl[2], Bl[3]);
    mma_bf16(a1, Al, Bh[2], Bh[3]);
}

// ---------------- main persistent kernel ----------------
__global__ void __launch_bounds__(THREADS, 1)
cgconv_mma_kernel(const float* __restrict__ x,
                  const float* __restrict__ bias,
                  float* __restrict__ out)
{
    extern __shared__ char smem[];
    const uint32_t sb = smem_u32(smem);
    const int tid  = threadIdx.x;
    const int wid  = tid >> 5;      // 0..7
    const int lane = tid & 31;

    const int p  = wid & 3;         // pair id
    const int h  = wid >> 2;        // px half (32 px)
    const int m1 = p;               // small m-block
    const int m2 = 7 - p;           // large m-block (uniform 9 kb-blocks/warp)

    // ---- stage W hi/lo into smem (A-frag build only) ----
    {
        const uint4* whi = reinterpret_cast<const uint4*>(g_Whi);
        const uint4* wlo = reinterpret_cast<const uint4*>(g_Wlo);
        for (int i = tid; i < C * C / 8; i += THREADS) {
            int row = i >> 4, c = i & 15;
            *reinterpret_cast<uint4*>(smem + S_W + row * W_PITCH_B + c * 16) = whi[i];
            *reinterpret_cast<uint4*>(smem + S_W + W_PLANE_B + row * W_PITCH_B + c * 16) = wlo[i];
        }
    }
    __syncthreads();

    // ---- register-resident A fragments (built once, 9 blocks/warp) ----
    uint32_t A1h[4][4], A1l[4][4], A2h[8][4], A2l[8][4];
    {
        const uint32_t arow    = (uint32_t)(lane & 15) * W_PITCH_B;
        const uint32_t acolsel = (uint32_t)(lane >> 4) * 16;
        const uint32_t whi_u = sb + S_W + arow + acolsel;
        const uint32_t wlo_u = sb + S_W + W_PLANE_B + arow + acolsel;
#pragma unroll
        for (int kb = 0; kb < 4; ++kb) {
            if (kb <= m1) {
                uint32_t off = (uint32_t)m1 * 16 * W_PITCH_B + (uint32_t)kb * 32;
                ldsm_x4(A1h[kb], whi_u + off);
                ldsm_x4(A1l[kb], wlo_u + off);
            }
        }
#pragma unroll
        for (int kb = 0; kb < 8; ++kb) {
            if (kb <= m2) {
                uint32_t off = (uint32_t)m2 * 16 * W_PITCH_B + (uint32_t)kb * 32;
                ldsm_x4(A2h[kb], whi_u + off);
                ldsm_x4(A2l[kb], wlo_u + off);
            }
        }
    }

    // ---- bias ----
    const int qr = lane >> 2;
    const int qj = lane & 3;
    const float b1lo = __ldg(bias + m1 * 16 + qr);
    const float b1hi = __ldg(bias + m1 * 16 + 8 + qr);
    const float b2lo = __ldg(bias + m2 * 16 + qr);
    const float b2hi = __ldg(bias + m2 * 16 + 8 + qr);

    // ---- B ldmatrix bases ----
    const uint32_t brow = (uint32_t)(lane & 15) * X_PITCH_B + (uint32_t)(lane >> 4) * 16;
    const uint32_t xhi_u = sb + S_X + brow + (uint32_t)h * 64;
    const uint32_t xlo_u = xhi_u + X_PLANE_B;

    // ---- producer / flush addressing ----
    const int pk_base = 16 * wid + (lane >> 4);   // k row / ch row base
    const int pk_px   = (lane & 15) * 4;          // px offset

    float* scratch = reinterpret_cast<float*>(smem + S_SCR);

    // ---- prefetch first tile ----
    uint4 pf[8];
    {
        int t0 = blockIdx.x;
        int b = t0 / TILES_PER_B;
        size_t xb = (size_t)b * C * HW + (size_t)(t0 - b * TILES_PER_B) * TILE_PX;
#pragma unroll
        for (int i = 0; i < 8; ++i)
            pf[i] = *reinterpret_cast<const uint4*>(x + xb + (size_t)(pk_base + 2 * i) * HW + pk_px);
    }

    size_t prev_obase = 0;
    int have_prev = 0;

    for (int t = blockIdx.x; t < NT; t += GRID) {
        const int b   = t / TILES_PER_B;
        const int px0 = (t - b * TILES_PER_B) * TILE_PX;
        const size_t obase = (size_t)b * C * HW + px0;

        __syncthreads();   // mma(t-1) X reads done; epi-STS(t-1) visible

        // ---- deferred flush: tile t-1 scratch -> gmem ----
        if (have_prev) {
#pragma unroll
            for (int i = 0; i < 8; ++i) {
                const int ch = pk_base + 2 * i;
                float4 v = *reinterpret_cast<const float4*>(
                    scratch + ch * SCRATCH_PITCH_W + pk_px);
                *reinterpret_cast<float4*>(out + prev_obase + (size_t)ch * HW + pk_px) = v;
            }
        }

        // ---- convert prefetched regs (tile t) -> bf16 hi/lo X planes ----
#pragma unroll
        for (int i = 0; i < 8; ++i) {
            const int k = pk_base + 2 * i;
            float fx = __uint_as_float(pf[i].x);
            float fy = __uint_as_float(pf[i].y);
            float fz = __uint_as_float(pf[i].z);
            float fw = __uint_as_float(pf[i].w);
            uint32_t h0 = packbf2(fx, fy);
            uint32_t h1 = packbf2(fz, fw);
            uint32_t l0 = packbf2(fx - __uint_as_float(h0 << 16),
                                  fy - __uint_as_float(h0 & 0xFFFF0000u));
            uint32_t l1 = packbf2(fz - __uint_as_float(h1 << 16),
                                  fw - __uint_as_float(h1 & 0xFFFF0000u));
            uint32_t off = (uint32_t)k * X_PITCH_B + (uint32_t)(lane & 15) * 8;
            *reinterpret_cast<uint2*>(smem + S_X + off)             = make_uint2(h0, h1);
            *reinterpret_cast<uint2*>(smem + S_X + X_PLANE_B + off) = make_uint2(l0, l1);
        }
        __syncthreads();   // X(t) ready; flush(t-1) complete everywhere

        // ---- prefetch tile t+GRID (hidden behind mma) ----
        {
            int tn = t + GRID;
            if (tn >= NT) tn = t;
            int bn = tn / TILES_PER_B;
            size_t xb = (size_t)bn * C * HW + (size_t)(tn - bn * TILES_PER_B) * TILE_PX;
#pragma unroll
            for (int i = 0; i < 8; ++i)
                pf[i] = *reinterpret_cast<const uint4*>(x + xb + (size_t)(pk_base + 2 * i) * HW + pk_px);
        }

        // ---- triangular GEMM, B software-pipelined across kb ----
        float acc[2][4][4];
#pragma unroll
        for (int mi = 0; mi < 2; ++mi)
#pragma unroll
            for (int j = 0; j < 4; ++j)
#pragma unroll
                for (int q = 0; q < 4; ++q) acc[mi][j][q] = 0.0f;

        uint32_t Bh[2][2][4], Bl[2][2][4];   // [buf][nt][4]
        // preload kb=0 (every warp has m2 >= 4 > 0)
        ldsm_x4_t(Bh[0][0], xhi_u);
        ldsm_x4_t(Bl[0][0], xlo_u);
        ldsm_x4_t(Bh[0][1], xhi_u + 32);
        ldsm_x4_t(Bl[0][1], xlo_u + 32);

#pragma unroll
        for (int kb = 0; kb < 8; ++kb) {
            if (kb <= m2) {
                const int cur = kb & 1;
                const int nxt = cur ^ 1;
                if (kb + 1 <= m2) {   // issue next kb's loads before this kb's mma
                    uint32_t boff = (uint32_t)(kb + 1) * 16 * X_PITCH_B;
                    ldsm_x4_t(Bh[nxt][0], xhi_u + boff);
                    ldsm_x4_t(Bl[nxt][0], xlo_u + boff);
                    ldsm_x4_t(Bh[nxt][1], xhi_u + boff + 32);
                    ldsm_x4_t(Bl[nxt][1], xlo_u + boff + 32);
                }
#pragma unroll
                for (int nt = 0; nt < 2; ++nt) {
                    mma3(acc[1][2 * nt], acc[1][2 * nt + 1],
                         A2h[kb], A2l[kb], Bh[cur][nt], Bl[cur][nt]);
                    if (kb < 4 && kb <= m1)
                        mma3(acc[0][2 * nt], acc[0][2 * nt + 1],
                             A1h[kb], A1l[kb], Bh[cur][nt], Bl[cur][nt]);
                }
            }
        }

        // ---- epilogue: bias + transpose into scratch ----
#pragma unroll
        for (int j = 0; j < 4; ++j) {
            acc[0][j][0] += b1lo; acc[0][j][1] += b1lo;
            acc[0][j][2] += b1hi; acc[0][j][3] += b1hi;
            acc[1][j][0] += b2lo; acc[1][j][1] += b2lo;
            acc[1][j][2] += b2hi; acc[1][j][3] += b2hi;
        }
#pragma unroll
        for (int mi = 0; mi < 2; ++mi) {
            const int m = mi ? m2 : m1;
            const int ch_lo = m * 16 + qr;
#pragma unroll
            for (int j = 0; j < 4; ++j) {
                const int px = h * 32 + 8 * j + 2 * qj;
                *reinterpret_cast<float2*>(scratch + ch_lo * SCRATCH_PITCH_W + px) =
                    make_float2(acc[mi][j][0], acc[mi][j][1]);
                *reinterpret_cast<float2*>(scratch + (ch_lo + 8) * SCRATCH_PITCH_W + px) =
                    make_float2(acc[mi][j][2], acc[mi][j][3]);
            }
        }

        prev_obase = obase;
        have_prev = 1;
    }

    // ---- flush final tile ----
    __syncthreads();
    if (have_prev) {
#pragma unroll
        for (int i = 0; i < 8; ++i) {
            const int ch = pk_base + 2 * i;
            float4 v = *reinterpret_cast<const float4*>(
                scratch + ch * SCRATCH_PITCH_W + pk_px);
            *reinterpret_cast<float4*>(out + prev_obase + (size_t)ch * HW + pk_px) = v;
        }
    }
}

extern "C" void kernel_launch(void* const* d_in, const int* in_sizes, int n_in,
                              void* d_out, int out_size)
{
    const float* x    = (const float*)d_in[0];
    const float* w    = (const float*)d_in[1];
    const float* bias = (const float*)d_in[2];
    float* out        = (float*)d_out;

    cudaFuncSetAttribute(cgconv_mma_kernel,
                         cudaFuncAttributeMaxDynamicSharedMemorySize, SMEM_TOTAL);

    build_w_kernel<<<C, C>>>(w);
    cgconv_mma_kernel<<<GRID, THREADS, SMEM_TOTAL>>>(x, bias, out);
}